// round 6
// baseline (speedup 1.0000x reference)
#include <cuda_runtime.h>
#include <cuda_bf16.h>
#include <math.h>
#include <stdint.h>

#define NPTS 4096
#define DIM  1024
#define NPOSD 7
#define NNEGD 4088
#define KSEL 17
#define ALPHA_C 30.0f
#define OFF_POS 4
#define OFF_NEG (4 + NPTS * NPOSD)

// GEMM: CTA tile 256x128, warp tile 64x64, K=3072 (bf16 split, K-packed), BK=32
#define BK 32
#define KITERS 96
#define STAGES 4
#define LDM 40                            // smem row stride in bf16 (80B)
#define A_BYTES (256 * LDM * 2)           // 20480
#define B_BYTES (128 * LDM * 2)           // 10240
#define STAGE_BYTES (A_BYTES + B_BYTES)   // 30720
#define GEMM_SMEM (STAGES * STAGE_BYTES)  // 122880
#define NCTA 272                          // sum over R<16 of (32-2R)

__device__ __nv_bfloat16 g_s1[NPTS * DIM];
__device__ __nv_bfloat16 g_s2[NPTS * DIM];
__device__ float g_sq[NPTS];
__device__ float g_loss[NPTS];
__device__ float g_psum[NPTS];
__device__ float g_nsum[NPTS];
__device__ int   g_ctr;

// ---------------------------------------------------------------------------
__device__ __forceinline__ uint32_t smem_u32(const void* p) {
    uint32_t a;
    asm("{ .reg .u64 t; cvta.to.shared.u64 t, %1; cvt.u32.u64 %0, t; }" : "=r"(a) : "l"(p));
    return a;
}
__device__ __forceinline__ void cp_async16(uint32_t dst, const void* src) {
    asm volatile("cp.async.cg.shared.global [%0], [%1], 16;" :: "r"(dst), "l"(src));
}
__device__ __forceinline__ void cp_commit() { asm volatile("cp.async.commit_group;"); }
template <int N>
__device__ __forceinline__ void cp_wait() {
    asm volatile("cp.async.wait_group %0;" :: "n"(N));
}
__device__ __forceinline__ void ldsm4(uint32_t* r, uint32_t addr) {
    asm volatile("ldmatrix.sync.aligned.m8n8.x4.shared.b16 {%0,%1,%2,%3}, [%4];"
                 : "=r"(r[0]), "=r"(r[1]), "=r"(r[2]), "=r"(r[3]) : "r"(addr));
}
__device__ __forceinline__ void mma16816(float* d, const uint32_t* a,
                                         uint32_t b0, uint32_t b1) {
    asm volatile("mma.sync.aligned.m16n8k16.row.col.f32.bf16.bf16.f32 "
                 "{%0,%1,%2,%3}, {%4,%5,%6,%7}, {%8,%9}, {%0,%1,%2,%3};"
                 : "+f"(d[0]), "+f"(d[1]), "+f"(d[2]), "+f"(d[3])
                 : "r"(a[0]), "r"(a[1]), "r"(a[2]), "r"(a[3]), "r"(b0), "r"(b1));
}

// ---------------------------------------------------------------------------
__device__ __forceinline__ float fast_exp(float a) {
    float y = a * 1.4426950408889634f;
    float n = rintf(y);
    float f = y - n;
    float p = 1.525273380405984e-5f;
    p = fmaf(p, f, 1.540353039338161e-4f);
    p = fmaf(p, f, 1.333355814642844e-3f);
    p = fmaf(p, f, 9.618129107628477e-3f);
    p = fmaf(p, f, 5.550410866482158e-2f);
    p = fmaf(p, f, 2.402265069591007e-1f);
    p = fmaf(p, f, 6.931471805599453e-1f);
    p = fmaf(p, f, 1.0f);
    int e = (int)n;
    return p * __int_as_float((e + 127) << 23);
}
__device__ __forceinline__ int out_index(int i, int j) {
    int lo = (i >> 3) << 3;
    unsigned rel = (unsigned)(j - lo);
    if (rel < 8u) {
        int p = j - lo - (j > i ? 1 : 0);
        return OFF_POS + i * NPOSD + p;
    }
    int p = (j < lo) ? j : (j - 8);
    return OFF_NEG + i * NNEGD + p;
}
__device__ __forceinline__ float block_sum256(float v, float* buf) {
    int t = threadIdx.x;
#pragma unroll
    for (int d = 16; d > 0; d >>= 1) v += __shfl_down_sync(0xFFFFFFFFu, v, d);
    if ((t & 31) == 0) buf[t >> 5] = v;
    __syncthreads();
    if (t < 32) {
        float x = (t < 8) ? buf[t] : 0.0f;
#pragma unroll
        for (int d = 4; d > 0; d >>= 1) x += __shfl_down_sync(0xFFFFFFFFu, x, d);
        if (t == 0) buf[0] = x;
    }
    __syncthreads();
    float r = buf[0];
    __syncthreads();
    return r;
}
__device__ __forceinline__ float block_min256(float v, float* buf) {
    int t = threadIdx.x;
#pragma unroll
    for (int d = 16; d > 0; d >>= 1) v = fminf(v, __shfl_down_sync(0xFFFFFFFFu, v, d));
    if ((t & 31) == 0) buf[t >> 5] = v;
    __syncthreads();
    if (t < 32) {
        float x = (t < 8) ? buf[t] : __int_as_float(0x7f800000);
#pragma unroll
        for (int d = 4; d > 0; d >>= 1) x = fminf(x, __shfl_down_sync(0xFFFFFFFFu, x, d));
        if (t == 0) buf[0] = x;
    }
    __syncthreads();
    float r = buf[0];
    __syncthreads();
    return r;
}

// ---------------------------------------------------------------------------
// Kernel 1: bf16 2-way split (row-major) + fused row squared norms + ctr reset
// ---------------------------------------------------------------------------
__global__ __launch_bounds__(128) void prep_kernel(const float* __restrict__ X) {
    int i = blockIdx.x, t = threadIdx.x;
    if (i == 0 && t == 0) g_ctr = 0;
    const float4* row = (const float4*)(X + (size_t)i * DIM);
    float4 x0 = row[t * 2], x1 = row[t * 2 + 1];
    float xs[8] = {x0.x, x0.y, x0.z, x0.w, x1.x, x1.y, x1.z, x1.w};
    unsigned int w1[4], w2[4];
    float s = 0.0f;
#pragma unroll
    for (int e = 0; e < 4; e++) {
        float xa = xs[2 * e], xb = xs[2 * e + 1];
        s = fmaf(xa, xa, fmaf(xb, xb, s));
        __nv_bfloat16 ha = __float2bfloat16(xa);
        __nv_bfloat16 hb = __float2bfloat16(xb);
        __nv_bfloat16 ra = __float2bfloat16(xa - __bfloat162float(ha));
        __nv_bfloat16 rb = __float2bfloat16(xb - __bfloat162float(hb));
        w1[e] = (unsigned)__bfloat16_as_ushort(ha) | ((unsigned)__bfloat16_as_ushort(hb) << 16);
        w2[e] = (unsigned)__bfloat16_as_ushort(ra) | ((unsigned)__bfloat16_as_ushort(rb) << 16);
    }
    size_t off = (size_t)i * DIM + t * 8;
    *(uint4*)(g_s1 + off) = make_uint4(w1[0], w1[1], w1[2], w1[3]);
    *(uint4*)(g_s2 + off) = make_uint4(w2[0], w2[1], w2[2], w2[3]);

    __shared__ float rbuf[4];
#pragma unroll
    for (int d = 16; d > 0; d >>= 1) s += __shfl_down_sync(0xFFFFFFFFu, s, d);
    if ((t & 31) == 0) rbuf[t >> 5] = s;
    __syncthreads();
    if (t == 0) g_sq[i] = rbuf[0] + rbuf[1] + rbuf[2] + rbuf[3];
}

// ---------------------------------------------------------------------------
// Kernel 2: bf16 HMMA GEMM, 256x128 tiles (272 CTAs, ~1.8 waves), warp tile
// 64x64, K=3072 packed split, 4-stage cp.async, single sync/iter, fused dist
// epilogue writing only col>row (direct + mirror).
// ---------------------------------------------------------------------------
__global__ __launch_bounds__(256) void gemm_dist_kernel(float* __restrict__ out) {
    extern __shared__ __align__(16) unsigned char smem_raw[];
    uint32_t sbase = smem_u32(smem_raw);

    // decode blockIdx -> (R: 256-row block, C: 128-col block), C >= 2R
    int rem = blockIdx.x, R = 0;
    while (rem >= 32 - 2 * R) { rem -= 32 - 2 * R; R++; }
    int C = 2 * R + rem;

    int tid = threadIdx.x;
    int wid = tid >> 5, lane = tid & 31;
    int wm = wid >> 1, wn = wid & 1;          // warp grid 4 x 2
    int mbase = wm * 64, nbase = wn * 64;

    const __nv_bfloat16* Asrc[3] = {g_s1, g_s1, g_s2};
    const __nv_bfloat16* Bsrc[3] = {g_s1, g_s2, g_s1};

    int browB = tid >> 1, bhalf = tid & 1;    // B: 128 rows, 2 threads/row

    float acc[4][8][4];
#pragma unroll
    for (int mt = 0; mt < 4; mt++)
#pragma unroll
        for (int nt = 0; nt < 8; nt++)
#pragma unroll
            for (int e = 0; e < 4; e++) acc[mt][nt][e] = 0.0f;

    auto issue_load = [&](int stage, int c) {
        int seg = c >> 5;
        int kk = (c & 31) * BK;
        uint32_t sA = sbase + stage * STAGE_BYTES;
        uint32_t sB = sA + A_BYTES;
        // A: thread tid loads full row tid (64B = 4 chunks)
        const __nv_bfloat16* ga = Asrc[seg] + (size_t)(R * 256 + tid) * DIM + kk;
        uint32_t dA = sA + (uint32_t)tid * (LDM * 2);
#pragma unroll
        for (int cch = 0; cch < 4; cch++)
            cp_async16(dA + cch * 16, (const char*)ga + cch * 16);
        // B: 2 threads per row, 32B halves
        const __nv_bfloat16* gb = Bsrc[seg] + (size_t)(C * 128 + browB) * DIM + kk + bhalf * 16;
        uint32_t dB = sB + (uint32_t)browB * (LDM * 2) + bhalf * 32;
        cp_async16(dB, gb);
        cp_async16(dB + 16, (const char*)gb + 16);
    };

#pragma unroll
    for (int s = 0; s < STAGES - 1; s++) { issue_load(s, s); cp_commit(); }

    int lrow = lane & 15, lcolsel = (lane >> 4) * 8;

    for (int c = 0; c < KITERS; c++) {
        cp_wait<STAGES - 2>();
        __syncthreads();
        int st = c & (STAGES - 1);
        uint32_t sA = sbase + st * STAGE_BYTES;
        uint32_t sB = sA + A_BYTES;
#pragma unroll
        for (int ks = 0; ks < 2; ks++) {
            uint32_t af[4][4], bf[4][4];
#pragma unroll
            for (int mt = 0; mt < 4; mt++)
                ldsm4(af[mt], sA + (uint32_t)((mbase + mt * 16 + lrow) * LDM
                                              + ks * 16 + lcolsel) * 2);
#pragma unroll
            for (int nb2 = 0; nb2 < 4; nb2++)
                ldsm4(bf[nb2], sB + (uint32_t)((nbase + nb2 * 16 + lrow) * LDM
                                               + ks * 16 + lcolsel) * 2);
#pragma unroll
            for (int mt = 0; mt < 4; mt++)
#pragma unroll
                for (int nt = 0; nt < 8; nt++)
                    mma16816(acc[mt][nt], af[mt], bf[nt >> 1][nt & 1],
                             bf[nt >> 1][(nt & 1) + 2]);
        }
        if (c + STAGES - 1 < KITERS)
            issue_load((c + STAGES - 1) & (STAGES - 1), c + STAGES - 1);
        cp_commit();
    }

    // ---- epilogue: dist + scatter, only col > row (direct + mirror) ----
    int r_in = lane >> 2, c_in = (lane & 3) * 2;
#pragma unroll
    for (int mt = 0; mt < 4; mt++) {
        int gr0 = R * 256 + mbase + mt * 16 + r_in;
        float sq_r0 = __ldg(&g_sq[gr0]);
        float sq_r1 = __ldg(&g_sq[gr0 + 8]);
#pragma unroll
        for (int nt = 0; nt < 8; nt++) {
            int gc0 = C * 128 + nbase + nt * 8 + c_in;
            float sq_c0 = __ldg(&g_sq[gc0]);
            float sq_c1 = __ldg(&g_sq[gc0 + 1]);
            float d00 = sqrtf(fmaxf(sq_r0 + sq_c0 - 2.0f * acc[mt][nt][0], 1e-12f));
            float d01 = sqrtf(fmaxf(sq_r0 + sq_c1 - 2.0f * acc[mt][nt][1], 1e-12f));
            float d10 = sqrtf(fmaxf(sq_r1 + sq_c0 - 2.0f * acc[mt][nt][2], 1e-12f));
            float d11 = sqrtf(fmaxf(sq_r1 + sq_c1 - 2.0f * acc[mt][nt][3], 1e-12f));
            if (gc0 > gr0) {
                out[out_index(gr0, gc0)] = d00;
                out[out_index(gc0, gr0)] = d00;
            }
            if (gc0 + 1 > gr0) {
                out[out_index(gr0, gc0 + 1)] = d01;
                out[out_index(gc0 + 1, gr0)] = d01;
            }
            if (gc0 > gr0 + 8) {
                out[out_index(gr0 + 8, gc0)] = d10;
                out[out_index(gc0, gr0 + 8)] = d10;
            }
            if (gc0 + 1 > gr0 + 8) {
                out[out_index(gr0 + 8, gc0 + 1)] = d11;
                out[out_index(gc0 + 1, gr0 + 8)] = d11;
            }
        }
    }
}

// ---------------------------------------------------------------------------
// Kernel 3: per-row exact 17th-smallest (radix select) + logits; last block
// does the final deterministic reduction into out[0..3].
// ---------------------------------------------------------------------------
__global__ __launch_bounds__(256) void row_select_kernel(float* __restrict__ out) {
    int i = blockIdx.x;
    int t = threadIdx.x;
    const float* pos = out + OFF_POS + i * NPOSD;
    const float* neg = out + OFF_NEG + (size_t)i * NNEGD;

    float v[16];
    float psum = 0.0f, nsum = 0.0f;
    float minpos = __int_as_float(0x7f800000);
#pragma unroll
    for (int s = 0; s < 16; s++) {
        int idx = t + (s << 8);
        float val;
        if (idx < NPOSD) {
            val = pos[idx];
            psum += val;
            minpos = fminf(minpos, val);
        } else if (idx < NPOSD + NNEGD) {
            val = neg[idx - NPOSD];
            nsum += val;
        } else {
            val = __int_as_float(0x7f800000);
        }
        v[s] = val;
    }

    __shared__ int hist[256];
    __shared__ int wsum[8];
    __shared__ int sel[2];
    unsigned prefix = 0u;
    int k = KSEL;
#pragma unroll
    for (int pass = 0; pass < 4; pass++) {
        int shift = 24 - pass * 8;
        hist[t] = 0;
        __syncthreads();
        unsigned pm = (pass == 0) ? 0u : (0xFFFFFFFFu << (shift + 8));
#pragma unroll
        for (int s = 0; s < 16; s++) {
            unsigned bb = __float_as_uint(v[s]);
            if ((bb & pm) == prefix) atomicAdd(&hist[(bb >> shift) & 255u], 1);
        }
        __syncthreads();
        int cnt = hist[t];
        int x = cnt;
#pragma unroll
        for (int d2 = 1; d2 < 32; d2 <<= 1) {
            int y = __shfl_up_sync(0xFFFFFFFFu, x, d2);
            if ((t & 31) >= d2) x += y;
        }
        if ((t & 31) == 31) wsum[t >> 5] = x;
        __syncthreads();
        if (t < 8) {
            int y = wsum[t];
#pragma unroll
            for (int d2 = 1; d2 < 8; d2 <<= 1) {
                int z = __shfl_up_sync(0xFFu, y, d2);
                if (t >= d2) y += z;
            }
            wsum[t] = y;
        }
        __syncthreads();
        int incl = x + ((t >= 32) ? wsum[(t >> 5) - 1] : 0);
        int excl = incl - cnt;
        if (incl >= k && excl < k) { sel[0] = t; sel[1] = excl; }
        __syncthreads();
        prefix |= ((unsigned)sel[0]) << shift;
        k -= sel[1];
        __syncthreads();
    }
    float thr = __uint_as_float(prefix);

    float pe = 0.0f, ne = 0.0f;
#pragma unroll
    for (int s = 0; s < 16; s++) {
        int idx = t + (s << 8);
        float d = v[s];
        if (idx < NPOSD + NNEGD && d < thr) {
            float e = fast_exp(ALPHA_C * (1.0f - d));
            if (idx < NPOSD) pe += e; else ne += e;
        }
    }

    __shared__ float rbuf[8];
    pe     = block_sum256(pe, rbuf);
    ne     = block_sum256(ne, rbuf);
    psum   = block_sum256(psum, rbuf);
    nsum   = block_sum256(nsum, rbuf);
    minpos = block_min256(minpos, rbuf);

    if (t == 0) {
        float pl = (minpos < thr) ? pe : fast_exp(ALPHA_C * (1.0f - minpos));
        g_loss[i] = logf(pl + ne) - logf(pl);
        g_psum[i] = psum;
        g_nsum[i] = nsum;
    }

    __threadfence();
    __shared__ int lastflag;
    if (t == 0) lastflag = (atomicAdd(&g_ctr, 1) == NPTS - 1) ? 1 : 0;
    __syncthreads();
    if (lastflag) {
        float ls = 0.0f, ac = 0.0f, ps = 0.0f, ns = 0.0f;
        for (int j = t; j < NPTS; j += 256) {
            float l = g_loss[j];
            ls += l;
            ac += (l < 0.6f) ? 1.0f : 0.0f;
            ps += g_psum[j];
            ns += g_nsum[j];
        }
        ls = block_sum256(ls, rbuf);
        ac = block_sum256(ac, rbuf);
        ps = block_sum256(ps, rbuf);
        ns = block_sum256(ns, rbuf);
        if (t == 0) {
            out[0] = ls / (float)NPTS;
            out[1] = ac / (float)NPTS;
            out[2] = ps / ((float)NPTS * (float)NPOSD);
            out[3] = ns / ((float)NPTS * (float)NNEGD);
        }
    }
}

// ---------------------------------------------------------------------------
extern "C" void kernel_launch(void* const* d_in, const int* in_sizes, int n_in,
                              void* d_out, int out_size) {
    const float* X = (const float*)d_in[0];
    float* out = (float*)d_out;
    (void)in_sizes; (void)n_in; (void)out_size;

    cudaFuncSetAttribute(gemm_dist_kernel, cudaFuncAttributeMaxDynamicSharedMemorySize,
                         GEMM_SMEM);
    prep_kernel<<<NPTS, 128>>>(X);
    gemm_dist_kernel<<<NCTA, 256, GEMM_SMEM>>>(out);
    row_select_kernel<<<NPTS, 256>>>(out);
}

// round 7
// speedup vs baseline: 1.1658x; 1.1658x over previous
#include <cuda_runtime.h>
#include <cuda_bf16.h>
#include <math.h>
#include <stdint.h>

#define NPTS 4096
#define DIM  1024
#define NPOSD 7
#define NNEGD 4088
#define KSEL 17
#define ALPHA_C 30.0f
#define OFF_POS 4
#define OFF_NEG (4 + NPTS * NPOSD)

// GEMM: CTA tile 128x128, warp tile 64x32, K=3072 (bf16 split, K-packed), BK=32
#define NB 32
#define BK 32
#define KITERS 96
#define STAGES 4
#define LDM 40                            // smem row stride in bf16 (80B)
#define STAGE_A (128 * LDM * 2)           // 10240
#define STAGE_BYTES (2 * STAGE_A)         // 20480
#define GEMM_SMEM (STAGES * STAGE_BYTES)  // 81920 -> 2 CTAs/SM

__device__ __nv_bfloat16 g_s1[NPTS * DIM];
__device__ __nv_bfloat16 g_s2[NPTS * DIM];
__device__ float g_sq[NPTS];
__device__ float g_loss[NPTS];
__device__ float g_psum[NPTS];
__device__ float g_nsum[NPTS];
__device__ int   g_ctr;

// ---------------------------------------------------------------------------
__device__ __forceinline__ uint32_t smem_u32(const void* p) {
    uint32_t a;
    asm("{ .reg .u64 t; cvta.to.shared.u64 t, %1; cvt.u32.u64 %0, t; }" : "=r"(a) : "l"(p));
    return a;
}
__device__ __forceinline__ void cp_async16(uint32_t dst, const void* src) {
    asm volatile("cp.async.cg.shared.global [%0], [%1], 16;" :: "r"(dst), "l"(src));
}
__device__ __forceinline__ void cp_commit() { asm volatile("cp.async.commit_group;"); }
template <int N>
__device__ __forceinline__ void cp_wait() {
    asm volatile("cp.async.wait_group %0;" :: "n"(N));
}
__device__ __forceinline__ void ldsm4(uint32_t* r, uint32_t addr) {
    asm volatile("ldmatrix.sync.aligned.m8n8.x4.shared.b16 {%0,%1,%2,%3}, [%4];"
                 : "=r"(r[0]), "=r"(r[1]), "=r"(r[2]), "=r"(r[3]) : "r"(addr));
}
__device__ __forceinline__ void mma16816(float* d, const uint32_t* a,
                                         uint32_t b0, uint32_t b1) {
    asm volatile("mma.sync.aligned.m16n8k16.row.col.f32.bf16.bf16.f32 "
                 "{%0,%1,%2,%3}, {%4,%5,%6,%7}, {%8,%9}, {%0,%1,%2,%3};"
                 : "+f"(d[0]), "+f"(d[1]), "+f"(d[2]), "+f"(d[3])
                 : "r"(a[0]), "r"(a[1]), "r"(a[2]), "r"(a[3]), "r"(b0), "r"(b1));
}

// ---------------------------------------------------------------------------
__device__ __forceinline__ float fast_exp(float a) {
    float y = a * 1.4426950408889634f;
    float n = rintf(y);
    float f = y - n;
    float p = 1.525273380405984e-5f;
    p = fmaf(p, f, 1.540353039338161e-4f);
    p = fmaf(p, f, 1.333355814642844e-3f);
    p = fmaf(p, f, 9.618129107628477e-3f);
    p = fmaf(p, f, 5.550410866482158e-2f);
    p = fmaf(p, f, 2.402265069591007e-1f);
    p = fmaf(p, f, 6.931471805599453e-1f);
    p = fmaf(p, f, 1.0f);
    int e = (int)n;
    return p * __int_as_float((e + 127) << 23);
}
__device__ __forceinline__ int out_index(int i, int j) {
    int lo = (i >> 3) << 3;
    unsigned rel = (unsigned)(j - lo);
    if (rel < 8u) {
        int p = j - lo - (j > i ? 1 : 0);
        return OFF_POS + i * NPOSD + p;
    }
    int p = (j < lo) ? j : (j - 8);
    return OFF_NEG + i * NNEGD + p;
}
__device__ __forceinline__ float block_sum256(float v, float* buf) {
    int t = threadIdx.x;
#pragma unroll
    for (int d = 16; d > 0; d >>= 1) v += __shfl_down_sync(0xFFFFFFFFu, v, d);
    if ((t & 31) == 0) buf[t >> 5] = v;
    __syncthreads();
    if (t < 32) {
        float x = (t < 8) ? buf[t] : 0.0f;
#pragma unroll
        for (int d = 4; d > 0; d >>= 1) x += __shfl_down_sync(0xFFFFFFFFu, x, d);
        if (t == 0) buf[0] = x;
    }
    __syncthreads();
    float r = buf[0];
    __syncthreads();
    return r;
}
__device__ __forceinline__ float block_min256(float v, float* buf) {
    int t = threadIdx.x;
#pragma unroll
    for (int d = 16; d > 0; d >>= 1) v = fminf(v, __shfl_down_sync(0xFFFFFFFFu, v, d));
    if ((t & 31) == 0) buf[t >> 5] = v;
    __syncthreads();
    if (t < 32) {
        float x = (t < 8) ? buf[t] : __int_as_float(0x7f800000);
#pragma unroll
        for (int d = 4; d > 0; d >>= 1) x = fminf(x, __shfl_down_sync(0xFFFFFFFFu, x, d));
        if (t == 0) buf[0] = x;
    }
    __syncthreads();
    float r = buf[0];
    __syncthreads();
    return r;
}

// ---------------------------------------------------------------------------
// Kernel 1: bf16 2-way split (row-major) + fused row squared norms + ctr reset
// ---------------------------------------------------------------------------
__global__ __launch_bounds__(128) void prep_kernel(const float* __restrict__ X) {
    int i = blockIdx.x, t = threadIdx.x;
    if (i == 0 && t == 0) g_ctr = 0;
    const float4* row = (const float4*)(X + (size_t)i * DIM);
    float4 x0 = row[t * 2], x1 = row[t * 2 + 1];
    float xs[8] = {x0.x, x0.y, x0.z, x0.w, x1.x, x1.y, x1.z, x1.w};
    unsigned int w1[4], w2[4];
    float s = 0.0f;
#pragma unroll
    for (int e = 0; e < 4; e++) {
        float xa = xs[2 * e], xb = xs[2 * e + 1];
        s = fmaf(xa, xa, fmaf(xb, xb, s));
        __nv_bfloat16 ha = __float2bfloat16(xa);
        __nv_bfloat16 hb = __float2bfloat16(xb);
        __nv_bfloat16 ra = __float2bfloat16(xa - __bfloat162float(ha));
        __nv_bfloat16 rb = __float2bfloat16(xb - __bfloat162float(hb));
        w1[e] = (unsigned)__bfloat16_as_ushort(ha) | ((unsigned)__bfloat16_as_ushort(hb) << 16);
        w2[e] = (unsigned)__bfloat16_as_ushort(ra) | ((unsigned)__bfloat16_as_ushort(rb) << 16);
    }
    size_t off = (size_t)i * DIM + t * 8;
    *(uint4*)(g_s1 + off) = make_uint4(w1[0], w1[1], w1[2], w1[3]);
    *(uint4*)(g_s2 + off) = make_uint4(w2[0], w2[1], w2[2], w2[3]);

    __shared__ float rbuf[4];
#pragma unroll
    for (int d = 16; d > 0; d >>= 1) s += __shfl_down_sync(0xFFFFFFFFu, s, d);
    if ((t & 31) == 0) rbuf[t >> 5] = s;
    __syncthreads();
    if (t == 0) g_sq[i] = rbuf[0] + rbuf[1] + rbuf[2] + rbuf[3];
}

// ---------------------------------------------------------------------------
// Kernel 2: bf16 HMMA GEMM, 128x128 triangular tiles (528 CTAs, 2 CTAs/SM =
// 1.78 waves), warp tile 64x32, K=3072 packed split, 4-stage cp.async,
// single sync/iter, fused dist epilogue.
// ---------------------------------------------------------------------------
__global__ __launch_bounds__(256, 2) void gemm_dist_kernel(float* __restrict__ out) {
    extern __shared__ __align__(16) unsigned char smem_raw[];
    uint32_t sbase = smem_u32(smem_raw);

    // decode blockIdx -> (bi <= bj) over 128-row blocks
    int b = blockIdx.x;
    int bi = 0, rem = b;
    while (rem >= NB - bi) { rem -= NB - bi; bi++; }
    int bj = bi + rem;

    int tid = threadIdx.x;
    int wid = tid >> 5, lane = tid & 31;
    int wm = wid >> 2, wn = wid & 3;         // warp grid 2 x 4
    int mbase = wm * 64, nbase = wn * 32;

    const __nv_bfloat16* Asrc[3] = {g_s1, g_s1, g_s2};
    const __nv_bfloat16* Bsrc[3] = {g_s1, g_s2, g_s1};

    int ldrow = tid >> 1;
    int ldhalf = tid & 1;

    float acc[4][4][4];
#pragma unroll
    for (int mt = 0; mt < 4; mt++)
#pragma unroll
        for (int nt = 0; nt < 4; nt++)
#pragma unroll
            for (int e = 0; e < 4; e++) acc[mt][nt][e] = 0.0f;

    auto issue_load = [&](int stage, int c) {
        int seg = c >> 5;
        int kk = (c & 31) * BK;
        uint32_t sA = sbase + stage * STAGE_BYTES;
        uint32_t sB = sA + STAGE_A;
        const __nv_bfloat16* ga = Asrc[seg] + (size_t)(bi * 128 + ldrow) * DIM + kk + ldhalf * 16;
        const __nv_bfloat16* gb = Bsrc[seg] + (size_t)(bj * 128 + ldrow) * DIM + kk + ldhalf * 16;
        uint32_t dA = sA + (uint32_t)(ldrow * LDM + ldhalf * 16) * 2;
        uint32_t dB = sB + (uint32_t)(ldrow * LDM + ldhalf * 16) * 2;
        cp_async16(dA, ga);
        cp_async16(dA + 16, (const char*)ga + 16);
        cp_async16(dB, gb);
        cp_async16(dB + 16, (const char*)gb + 16);
    };

#pragma unroll
    for (int s = 0; s < STAGES - 1; s++) { issue_load(s, s); cp_commit(); }

    int lrow = lane & 15, lcolsel = (lane >> 4) * 8;

    for (int c = 0; c < KITERS; c++) {
        cp_wait<STAGES - 2>();
        __syncthreads();
        int st = c & (STAGES - 1);
        uint32_t sA = sbase + st * STAGE_BYTES;
        uint32_t sB = sA + STAGE_A;
#pragma unroll
        for (int ks = 0; ks < 2; ks++) {
            uint32_t af[4][4], bf[2][4];
#pragma unroll
            for (int mt = 0; mt < 4; mt++)
                ldsm4(af[mt], sA + (uint32_t)((mbase + mt * 16 + lrow) * LDM
                                              + ks * 16 + lcolsel) * 2);
#pragma unroll
            for (int nb2 = 0; nb2 < 2; nb2++)
                ldsm4(bf[nb2], sB + (uint32_t)((nbase + nb2 * 16 + lrow) * LDM
                                               + ks * 16 + lcolsel) * 2);
#pragma unroll
            for (int mt = 0; mt < 4; mt++)
#pragma unroll
                for (int nt = 0; nt < 4; nt++)
                    mma16816(acc[mt][nt], af[mt], bf[nt >> 1][nt & 1],
                             bf[nt >> 1][(nt & 1) + 2]);
        }
        if (c + STAGES - 1 < KITERS)
            issue_load((c + STAGES - 1) & (STAGES - 1), c + STAGES - 1);
        cp_commit();
    }

    // ---- epilogue: dist + scatter (direct + mirror) ----
    bool diag = (bi == bj);
    int r_in = lane >> 2, c_in = (lane & 3) * 2;
#pragma unroll
    for (int mt = 0; mt < 4; mt++) {
        int gr0 = bi * 128 + mbase + mt * 16 + r_in;
        float sq_r0 = __ldg(&g_sq[gr0]);
        float sq_r1 = __ldg(&g_sq[gr0 + 8]);
#pragma unroll
        for (int nt = 0; nt < 4; nt++) {
            int gc0 = bj * 128 + nbase + nt * 8 + c_in;
            float sq_c0 = __ldg(&g_sq[gc0]);
            float sq_c1 = __ldg(&g_sq[gc0 + 1]);
            float d00 = sqrtf(fmaxf(sq_r0 + sq_c0 - 2.0f * acc[mt][nt][0], 1e-12f));
            float d01 = sqrtf(fmaxf(sq_r0 + sq_c1 - 2.0f * acc[mt][nt][1], 1e-12f));
            float d10 = sqrtf(fmaxf(sq_r1 + sq_c0 - 2.0f * acc[mt][nt][2], 1e-12f));
            float d11 = sqrtf(fmaxf(sq_r1 + sq_c1 - 2.0f * acc[mt][nt][3], 1e-12f));
            if (diag) {
                if (gr0 != gc0)         out[out_index(gr0, gc0)] = d00;
                if (gr0 != gc0 + 1)     out[out_index(gr0, gc0 + 1)] = d01;
                if (gr0 + 8 != gc0)     out[out_index(gr0 + 8, gc0)] = d10;
                if (gr0 + 8 != gc0 + 1) out[out_index(gr0 + 8, gc0 + 1)] = d11;
            } else {
                out[out_index(gr0, gc0)] = d00;
                out[out_index(gc0, gr0)] = d00;
                out[out_index(gr0, gc0 + 1)] = d01;
                out[out_index(gc0 + 1, gr0)] = d01;
                out[out_index(gr0 + 8, gc0)] = d10;
                out[out_index(gc0, gr0 + 8)] = d10;
                out[out_index(gr0 + 8, gc0 + 1)] = d11;
                out[out_index(gc0 + 1, gr0 + 8)] = d11;
            }
        }
    }
}

// ---------------------------------------------------------------------------
// Kernel 3: per-row exact 17th-smallest (radix select) + logits; last block
// does the final deterministic reduction into out[0..3].
// ---------------------------------------------------------------------------
__global__ __launch_bounds__(256) void row_select_kernel(float* __restrict__ out) {
    int i = blockIdx.x;
    int t = threadIdx.x;
    const float* pos = out + OFF_POS + i * NPOSD;
    const float* neg = out + OFF_NEG + (size_t)i * NNEGD;

    float v[16];
    float psum = 0.0f, nsum = 0.0f;
    float minpos = __int_as_float(0x7f800000);
#pragma unroll
    for (int s = 0; s < 16; s++) {
        int idx = t + (s << 8);
        float val;
        if (idx < NPOSD) {
            val = pos[idx];
            psum += val;
            minpos = fminf(minpos, val);
        } else if (idx < NPOSD + NNEGD) {
            val = neg[idx - NPOSD];
            nsum += val;
        } else {
            val = __int_as_float(0x7f800000);
        }
        v[s] = val;
    }

    __shared__ int hist[256];
    __shared__ int wsum[8];
    __shared__ int sel[2];
    unsigned prefix = 0u;
    int k = KSEL;
#pragma unroll
    for (int pass = 0; pass < 4; pass++) {
        int shift = 24 - pass * 8;
        hist[t] = 0;
        __syncthreads();
        unsigned pm = (pass == 0) ? 0u : (0xFFFFFFFFu << (shift + 8));
#pragma unroll
        for (int s = 0; s < 16; s++) {
            unsigned bb = __float_as_uint(v[s]);
            if ((bb & pm) == prefix) atomicAdd(&hist[(bb >> shift) & 255u], 1);
        }
        __syncthreads();
        int cnt = hist[t];
        int x = cnt;
#pragma unroll
        for (int d2 = 1; d2 < 32; d2 <<= 1) {
            int y = __shfl_up_sync(0xFFFFFFFFu, x, d2);
            if ((t & 31) >= d2) x += y;
        }
        if ((t & 31) == 31) wsum[t >> 5] = x;
        __syncthreads();
        if (t < 8) {
            int y = wsum[t];
#pragma unroll
            for (int d2 = 1; d2 < 8; d2 <<= 1) {
                int z = __shfl_up_sync(0xFFu, y, d2);
                if (t >= d2) y += z;
            }
            wsum[t] = y;
        }
        __syncthreads();
        int incl = x + ((t >= 32) ? wsum[(t >> 5) - 1] : 0);
        int excl = incl - cnt;
        if (incl >= k && excl < k) { sel[0] = t; sel[1] = excl; }
        __syncthreads();
        prefix |= ((unsigned)sel[0]) << shift;
        k -= sel[1];
        __syncthreads();
    }
    float thr = __uint_as_float(prefix);

    float pe = 0.0f, ne = 0.0f;
#pragma unroll
    for (int s = 0; s < 16; s++) {
        int idx = t + (s << 8);
        float d = v[s];
        if (idx < NPOSD + NNEGD && d < thr) {
            float e = fast_exp(ALPHA_C * (1.0f - d));
            if (idx < NPOSD) pe += e; else ne += e;
        }
    }

    __shared__ float rbuf[8];
    pe     = block_sum256(pe, rbuf);
    ne     = block_sum256(ne, rbuf);
    psum   = block_sum256(psum, rbuf);
    nsum   = block_sum256(nsum, rbuf);
    minpos = block_min256(minpos, rbuf);

    if (t == 0) {
        float pl = (minpos < thr) ? pe : fast_exp(ALPHA_C * (1.0f - minpos));
        g_loss[i] = logf(pl + ne) - logf(pl);
        g_psum[i] = psum;
        g_nsum[i] = nsum;
    }

    __threadfence();
    __shared__ int lastflag;
    if (t == 0) lastflag = (atomicAdd(&g_ctr, 1) == NPTS - 1) ? 1 : 0;
    __syncthreads();
    if (lastflag) {
        float ls = 0.0f, ac = 0.0f, ps = 0.0f, ns = 0.0f;
        for (int j = t; j < NPTS; j += 256) {
            float l = g_loss[j];
            ls += l;
            ac += (l < 0.6f) ? 1.0f : 0.0f;
            ps += g_psum[j];
            ns += g_nsum[j];
        }
        ls = block_sum256(ls, rbuf);
        ac = block_sum256(ac, rbuf);
        ps = block_sum256(ps, rbuf);
        ns = block_sum256(ns, rbuf);
        if (t == 0) {
            out[0] = ls / (float)NPTS;
            out[1] = ac / (float)NPTS;
            out[2] = ps / ((float)NPTS * (float)NPOSD);
            out[3] = ns / ((float)NPTS * (float)NNEGD);
        }
    }
}

// ---------------------------------------------------------------------------
extern "C" void kernel_launch(void* const* d_in, const int* in_sizes, int n_in,
                              void* d_out, int out_size) {
    const float* X = (const float*)d_in[0];
    float* out = (float*)d_out;
    (void)in_sizes; (void)n_in; (void)out_size;

    cudaFuncSetAttribute(gemm_dist_kernel, cudaFuncAttributeMaxDynamicSharedMemorySize,
                         GEMM_SMEM);
    prep_kernel<<<NPTS, 128>>>(X);
    gemm_dist_kernel<<<NB * (NB + 1) / 2, 256, GEMM_SMEM>>>(out);
    row_select_kernel<<<NPTS, 256>>>(out);
}

// round 8
// speedup vs baseline: 1.2824x; 1.1000x over previous
#include <cuda_runtime.h>
#include <cuda_bf16.h>
#include <math.h>
#include <stdint.h>

#define NPTS 4096
#define DIM  1024
#define NPOSD 7
#define NNEGD 4088
#define KSEL 17
#define ALPHA_C 30.0f
#define OFF_POS 4
#define OFF_NEG (4 + NPTS * NPOSD)

// GEMM: CTA tile 128x128, warp tile 64x32, K=3072 (bf16 split, K-packed), BK=64
#define NB 32
#define BK 64
#define KITERS 48                         // 3072/64
#define STAGES 3
#define TILE_BYTES (128 * 128)            // 16384: 128 rows x 128B (SW128 swizzled)
#define STAGE_BYTES (2 * TILE_BYTES)      // 32768 (A + B)
#define GEMM_SMEM (STAGES * STAGE_BYTES)  // 98304 -> 2 CTAs/SM (192KB)

__device__ __nv_bfloat16 g_s1[NPTS * DIM];
__device__ __nv_bfloat16 g_s2[NPTS * DIM];
__device__ float g_sq[NPTS];
__device__ float g_loss[NPTS];
__device__ float g_psum[NPTS];
__device__ float g_nsum[NPTS];
__device__ int   g_ctr;

// ---------------------------------------------------------------------------
__device__ __forceinline__ uint32_t smem_u32(const void* p) {
    uint32_t a;
    asm("{ .reg .u64 t; cvta.to.shared.u64 t, %1; cvt.u32.u64 %0, t; }" : "=r"(a) : "l"(p));
    return a;
}
__device__ __forceinline__ void cp_async16(uint32_t dst, const void* src) {
    asm volatile("cp.async.cg.shared.global [%0], [%1], 16;" :: "r"(dst), "l"(src));
}
__device__ __forceinline__ void cp_commit() { asm volatile("cp.async.commit_group;"); }
template <int N>
__device__ __forceinline__ void cp_wait() {
    asm volatile("cp.async.wait_group %0;" :: "n"(N));
}
__device__ __forceinline__ void ldsm4(uint32_t* r, uint32_t addr) {
    asm volatile("ldmatrix.sync.aligned.m8n8.x4.shared.b16 {%0,%1,%2,%3}, [%4];"
                 : "=r"(r[0]), "=r"(r[1]), "=r"(r[2]), "=r"(r[3]) : "r"(addr));
}
__device__ __forceinline__ void mma16816(float* d, const uint32_t* a,
                                         uint32_t b0, uint32_t b1) {
    asm volatile("mma.sync.aligned.m16n8k16.row.col.f32.bf16.bf16.f32 "
                 "{%0,%1,%2,%3}, {%4,%5,%6,%7}, {%8,%9}, {%0,%1,%2,%3};"
                 : "+f"(d[0]), "+f"(d[1]), "+f"(d[2]), "+f"(d[3])
                 : "r"(a[0]), "r"(a[1]), "r"(a[2]), "r"(a[3]), "r"(b0), "r"(b1));
}

// ---------------------------------------------------------------------------
__device__ __forceinline__ float fast_exp(float a) {
    float y = a * 1.4426950408889634f;
    float n = rintf(y);
    float f = y - n;
    float p = 1.525273380405984e-5f;
    p = fmaf(p, f, 1.540353039338161e-4f);
    p = fmaf(p, f, 1.333355814642844e-3f);
    p = fmaf(p, f, 9.618129107628477e-3f);
    p = fmaf(p, f, 5.550410866482158e-2f);
    p = fmaf(p, f, 2.402265069591007e-1f);
    p = fmaf(p, f, 6.931471805599453e-1f);
    p = fmaf(p, f, 1.0f);
    int e = (int)n;
    return p * __int_as_float((e + 127) << 23);
}
__device__ __forceinline__ int out_index(int i, int j) {
    int lo = (i >> 3) << 3;
    unsigned rel = (unsigned)(j - lo);
    if (rel < 8u) {
        int p = j - lo - (j > i ? 1 : 0);
        return OFF_POS + i * NPOSD + p;
    }
    int p = (j < lo) ? j : (j - 8);
    return OFF_NEG + i * NNEGD + p;
}
__device__ __forceinline__ float block_sum256(float v, float* buf) {
    int t = threadIdx.x;
#pragma unroll
    for (int d = 16; d > 0; d >>= 1) v += __shfl_down_sync(0xFFFFFFFFu, v, d);
    if ((t & 31) == 0) buf[t >> 5] = v;
    __syncthreads();
    if (t < 32) {
        float x = (t < 8) ? buf[t] : 0.0f;
#pragma unroll
        for (int d = 4; d > 0; d >>= 1) x += __shfl_down_sync(0xFFFFFFFFu, x, d);
        if (t == 0) buf[0] = x;
    }
    __syncthreads();
    float r = buf[0];
    __syncthreads();
    return r;
}
__device__ __forceinline__ float block_min256(float v, float* buf) {
    int t = threadIdx.x;
#pragma unroll
    for (int d = 16; d > 0; d >>= 1) v = fminf(v, __shfl_down_sync(0xFFFFFFFFu, v, d));
    if ((t & 31) == 0) buf[t >> 5] = v;
    __syncthreads();
    if (t < 32) {
        float x = (t < 8) ? buf[t] : __int_as_float(0x7f800000);
#pragma unroll
        for (int d = 4; d > 0; d >>= 1) x = fminf(x, __shfl_down_sync(0xFFFFFFFFu, x, d));
        if (t == 0) buf[0] = x;
    }
    __syncthreads();
    float r = buf[0];
    __syncthreads();
    return r;
}

// ---------------------------------------------------------------------------
// Kernel 1: bf16 2-way split (row-major) + fused row squared norms + ctr reset
// ---------------------------------------------------------------------------
__global__ __launch_bounds__(128) void prep_kernel(const float* __restrict__ X) {
    int i = blockIdx.x, t = threadIdx.x;
    if (i == 0 && t == 0) g_ctr = 0;
    const float4* row = (const float4*)(X + (size_t)i * DIM);
    float4 x0 = row[t * 2], x1 = row[t * 2 + 1];
    float xs[8] = {x0.x, x0.y, x0.z, x0.w, x1.x, x1.y, x1.z, x1.w};
    unsigned int w1[4], w2[4];
    float s = 0.0f;
#pragma unroll
    for (int e = 0; e < 4; e++) {
        float xa = xs[2 * e], xb = xs[2 * e + 1];
        s = fmaf(xa, xa, fmaf(xb, xb, s));
        __nv_bfloat16 ha = __float2bfloat16(xa);
        __nv_bfloat16 hb = __float2bfloat16(xb);
        __nv_bfloat16 ra = __float2bfloat16(xa - __bfloat162float(ha));
        __nv_bfloat16 rb = __float2bfloat16(xb - __bfloat162float(hb));
        w1[e] = (unsigned)__bfloat16_as_ushort(ha) | ((unsigned)__bfloat16_as_ushort(hb) << 16);
        w2[e] = (unsigned)__bfloat16_as_ushort(ra) | ((unsigned)__bfloat16_as_ushort(rb) << 16);
    }
    size_t off = (size_t)i * DIM + t * 8;
    *(uint4*)(g_s1 + off) = make_uint4(w1[0], w1[1], w1[2], w1[3]);
    *(uint4*)(g_s2 + off) = make_uint4(w2[0], w2[1], w2[2], w2[3]);

    __shared__ float rbuf[4];
#pragma unroll
    for (int d = 16; d > 0; d >>= 1) s += __shfl_down_sync(0xFFFFFFFFu, s, d);
    if ((t & 31) == 0) rbuf[t >> 5] = s;
    __syncthreads();
    if (t == 0) g_sq[i] = rbuf[0] + rbuf[1] + rbuf[2] + rbuf[3];
}

// ---------------------------------------------------------------------------
// Kernel 2: bf16 HMMA GEMM, 128x128 triangular tiles (528 CTAs, 2 CTAs/SM),
// warp tile 64x32, BK=64 with SW128 XOR swizzle (conflict-free ldmatrix),
// 3-stage cp.async, single sync/iter, fused dist epilogue.
// ---------------------------------------------------------------------------
__global__ __launch_bounds__(256, 2) void gemm_dist_kernel(float* __restrict__ out) {
    extern __shared__ __align__(128) unsigned char smem_raw[];
    uint32_t sbase = smem_u32(smem_raw);

    // decode blockIdx -> (bi <= bj) over 128-row blocks
    int b = blockIdx.x;
    int bi = 0, rem = b;
    while (rem >= NB - bi) { rem -= NB - bi; bi++; }
    int bj = bi + rem;

    int tid = threadIdx.x;
    int wid = tid >> 5, lane = tid & 31;
    int wm = wid >> 2, wn = wid & 3;         // warp grid 2 x 4
    int mbase = wm * 64, nbase = wn * 32;

    const __nv_bfloat16* Asrc[3] = {g_s1, g_s1, g_s2};
    const __nv_bfloat16* Bsrc[3] = {g_s1, g_s2, g_s1};

    // cp.async mapping: thread t -> row = t>>1 (0..127), 4 chunks of 16B
    int ldrow = tid >> 1;
    int ldq = (tid & 1) * 4;                 // chunk base 0 or 4

    float acc[4][4][4];
#pragma unroll
    for (int mt = 0; mt < 4; mt++)
#pragma unroll
        for (int nt = 0; nt < 4; nt++)
#pragma unroll
            for (int e = 0; e < 4; e++) acc[mt][nt][e] = 0.0f;

    auto issue_load = [&](int stage, int c) {
        int seg = c >> 4;                    // 16 iters of 64 per K-segment
        int kk = (c & 15) * BK;              // bf16 offset within 1024
        uint32_t sA = sbase + stage * STAGE_BYTES;
        uint32_t sB = sA + TILE_BYTES;
        const __nv_bfloat16* ga = Asrc[seg] + (size_t)(bi * 128 + ldrow) * DIM + kk;
        const __nv_bfloat16* gb = Bsrc[seg] + (size_t)(bj * 128 + ldrow) * DIM + kk;
        uint32_t rowoff = (uint32_t)ldrow * 128;
        uint32_t r7 = (uint32_t)(ldrow & 7);
#pragma unroll
        for (int j = 0; j < 4; j++) {
            uint32_t ch = (uint32_t)(ldq + j);
            uint32_t sw = rowoff + ((ch ^ r7) << 4);
            cp_async16(sA + sw, (const char*)ga + ch * 16);
            cp_async16(sB + sw, (const char*)gb + ch * 16);
        }
    };

#pragma unroll
    for (int s = 0; s < STAGES - 1; s++) { issue_load(s, s); cp_commit(); }

    int lrow = lane & 15, lch = lane >> 4;   // ldmatrix: row within 16, col-half

    int st = 0, ld_st = STAGES - 1;
    for (int c = 0; c < KITERS; c++) {
        cp_wait<STAGES - 2>();
        __syncthreads();
        uint32_t sA = sbase + st * STAGE_BYTES;
        uint32_t sB = sA + TILE_BYTES;
#pragma unroll
        for (int ks = 0; ks < 4; ks++) {
            uint32_t af[4][4], bf[2][4];
            uint32_t chsel = (uint32_t)(ks * 2 + lch);
#pragma unroll
            for (int mt = 0; mt < 4; mt++) {
                uint32_t r = (uint32_t)(mbase + mt * 16 + lrow);
                ldsm4(af[mt], sA + r * 128 + ((chsel ^ (r & 7)) << 4));
            }
#pragma unroll
            for (int nb2 = 0; nb2 < 2; nb2++) {
                uint32_t r = (uint32_t)(nbase + nb2 * 16 + lrow);
                ldsm4(bf[nb2], sB + r * 128 + ((chsel ^ (r & 7)) << 4));
            }
#pragma unroll
            for (int mt = 0; mt < 4; mt++)
#pragma unroll
                for (int nt = 0; nt < 4; nt++)
                    mma16816(acc[mt][nt], af[mt], bf[nt >> 1][nt & 1],
                             bf[nt >> 1][(nt & 1) + 2]);
        }
        if (c + STAGES - 1 < KITERS) issue_load(ld_st, c + STAGES - 1);
        cp_commit();
        st = (st == STAGES - 1) ? 0 : st + 1;
        ld_st = (ld_st == STAGES - 1) ? 0 : ld_st + 1;
    }

    // ---- epilogue: dist + scatter (direct + mirror) ----
    bool diag = (bi == bj);
    int r_in = lane >> 2, c_in = (lane & 3) * 2;
#pragma unroll
    for (int mt = 0; mt < 4; mt++) {
        int gr0 = bi * 128 + mbase + mt * 16 + r_in;
        float sq_r0 = __ldg(&g_sq[gr0]);
        float sq_r1 = __ldg(&g_sq[gr0 + 8]);
#pragma unroll
        for (int nt = 0; nt < 4; nt++) {
            int gc0 = bj * 128 + nbase + nt * 8 + c_in;
            float sq_c0 = __ldg(&g_sq[gc0]);
            float sq_c1 = __ldg(&g_sq[gc0 + 1]);
            float d00 = sqrtf(fmaxf(sq_r0 + sq_c0 - 2.0f * acc[mt][nt][0], 1e-12f));
            float d01 = sqrtf(fmaxf(sq_r0 + sq_c1 - 2.0f * acc[mt][nt][1], 1e-12f));
            float d10 = sqrtf(fmaxf(sq_r1 + sq_c0 - 2.0f * acc[mt][nt][2], 1e-12f));
            float d11 = sqrtf(fmaxf(sq_r1 + sq_c1 - 2.0f * acc[mt][nt][3], 1e-12f));
            if (diag) {
                if (gr0 != gc0)         out[out_index(gr0, gc0)] = d00;
                if (gr0 != gc0 + 1)     out[out_index(gr0, gc0 + 1)] = d01;
                if (gr0 + 8 != gc0)     out[out_index(gr0 + 8, gc0)] = d10;
                if (gr0 + 8 != gc0 + 1) out[out_index(gr0 + 8, gc0 + 1)] = d11;
            } else {
                out[out_index(gr0, gc0)] = d00;
                out[out_index(gc0, gr0)] = d00;
                out[out_index(gr0, gc0 + 1)] = d01;
                out[out_index(gc0 + 1, gr0)] = d01;
                out[out_index(gr0 + 8, gc0)] = d10;
                out[out_index(gc0, gr0 + 8)] = d10;
                out[out_index(gr0 + 8, gc0 + 1)] = d11;
                out[out_index(gc0 + 1, gr0 + 8)] = d11;
            }
        }
    }
}

// ---------------------------------------------------------------------------
// Kernel 3: per-row exact 17th-smallest (radix select) + logits; last block
// does the final deterministic reduction into out[0..3].
// ---------------------------------------------------------------------------
__global__ __launch_bounds__(256) void row_select_kernel(float* __restrict__ out) {
    int i = blockIdx.x;
    int t = threadIdx.x;
    const float* pos = out + OFF_POS + i * NPOSD;
    const float* neg = out + OFF_NEG + (size_t)i * NNEGD;

    float v[16];
    float psum = 0.0f, nsum = 0.0f;
    float minpos = __int_as_float(0x7f800000);
#pragma unroll
    for (int s = 0; s < 16; s++) {
        int idx = t + (s << 8);
        float val;
        if (idx < NPOSD) {
            val = pos[idx];
            psum += val;
            minpos = fminf(minpos, val);
        } else if (idx < NPOSD + NNEGD) {
            val = neg[idx - NPOSD];
            nsum += val;
        } else {
            val = __int_as_float(0x7f800000);
        }
        v[s] = val;
    }

    __shared__ int hist[256];
    __shared__ int wsum[8];
    __shared__ int sel[2];
    unsigned prefix = 0u;
    int k = KSEL;
#pragma unroll
    for (int pass = 0; pass < 4; pass++) {
        int shift = 24 - pass * 8;
        hist[t] = 0;
        __syncthreads();
        unsigned pm = (pass == 0) ? 0u : (0xFFFFFFFFu << (shift + 8));
#pragma unroll
        for (int s = 0; s < 16; s++) {
            unsigned bb = __float_as_uint(v[s]);
            if ((bb & pm) == prefix) atomicAdd(&hist[(bb >> shift) & 255u], 1);
        }
        __syncthreads();
        int cnt = hist[t];
        int x = cnt;
#pragma unroll
        for (int d2 = 1; d2 < 32; d2 <<= 1) {
            int y = __shfl_up_sync(0xFFFFFFFFu, x, d2);
            if ((t & 31) >= d2) x += y;
        }
        if ((t & 31) == 31) wsum[t >> 5] = x;
        __syncthreads();
        if (t < 8) {
            int y = wsum[t];
#pragma unroll
            for (int d2 = 1; d2 < 8; d2 <<= 1) {
                int z = __shfl_up_sync(0xFFu, y, d2);
                if (t >= d2) y += z;
            }
            wsum[t] = y;
        }
        __syncthreads();
        int incl = x + ((t >= 32) ? wsum[(t >> 5) - 1] : 0);
        int excl = incl - cnt;
        if (incl >= k && excl < k) { sel[0] = t; sel[1] = excl; }
        __syncthreads();
        prefix |= ((unsigned)sel[0]) << shift;
        k -= sel[1];
        __syncthreads();
    }
    float thr = __uint_as_float(prefix);

    float pe = 0.0f, ne = 0.0f;
#pragma unroll
    for (int s = 0; s < 16; s++) {
        int idx = t + (s << 8);
        float d = v[s];
        if (idx < NPOSD + NNEGD && d < thr) {
            float e = fast_exp(ALPHA_C * (1.0f - d));
            if (idx < NPOSD) pe += e; else ne += e;
        }
    }

    __shared__ float rbuf[8];
    pe     = block_sum256(pe, rbuf);
    ne     = block_sum256(ne, rbuf);
    psum   = block_sum256(psum, rbuf);
    nsum   = block_sum256(nsum, rbuf);
    minpos = block_min256(minpos, rbuf);

    if (t == 0) {
        float pl = (minpos < thr) ? pe : fast_exp(ALPHA_C * (1.0f - minpos));
        g_loss[i] = logf(pl + ne) - logf(pl);
        g_psum[i] = psum;
        g_nsum[i] = nsum;
    }

    __threadfence();
    __shared__ int lastflag;
    if (t == 0) lastflag = (atomicAdd(&g_ctr, 1) == NPTS - 1) ? 1 : 0;
    __syncthreads();
    if (lastflag) {
        float ls = 0.0f, ac = 0.0f, ps = 0.0f, ns = 0.0f;
        for (int j = t; j < NPTS; j += 256) {
            float l = g_loss[j];
            ls += l;
            ac += (l < 0.6f) ? 1.0f : 0.0f;
            ps += g_psum[j];
            ns += g_nsum[j];
        }
        ls = block_sum256(ls, rbuf);
        ac = block_sum256(ac, rbuf);
        ps = block_sum256(ps, rbuf);
        ns = block_sum256(ns, rbuf);
        if (t == 0) {
            out[0] = ls / (float)NPTS;
            out[1] = ac / (float)NPTS;
            out[2] = ps / ((float)NPTS * (float)NPOSD);
            out[3] = ns / ((float)NPTS * (float)NNEGD);
        }
    }
}

// ---------------------------------------------------------------------------
extern "C" void kernel_launch(void* const* d_in, const int* in_sizes, int n_in,
                              void* d_out, int out_size) {
    const float* X = (const float*)d_in[0];
    float* out = (float*)d_out;
    (void)in_sizes; (void)n_in; (void)out_size;

    cudaFuncSetAttribute(gemm_dist_kernel, cudaFuncAttributeMaxDynamicSharedMemorySize,
                         GEMM_SMEM);
    prep_kernel<<<NPTS, 128>>>(X);
    gemm_dist_kernel<<<NB * (NB + 1) / 2, 256, GEMM_SMEM>>>(out);
    row_select_kernel<<<NPTS, 256>>>(out);
}

// round 9
// speedup vs baseline: 3.1318x; 2.4422x over previous
#include <cuda_runtime.h>
#include <cuda_bf16.h>
#include <math.h>
#include <stdint.h>

#define NPTS 4096
#define DIM  1024
#define NPOSD 7
#define NNEGD 4088
#define KSEL 17
#define ALPHA_C 30.0f
#define OFF_POS 4
#define OFF_NEG (4 + NPTS * NPOSD)

// GEMM: CTA tile 128x128, warp tile 64x32, int8 single-pass K=1024, BK=128B
#define NB 32
#define KITERS 8                          // 1024 int8 / 128 per iter
#define STAGES 3
#define TILE_BYTES (128 * 128)            // 16384: 128 rows x 128B (SW128 swizzled)
#define STAGE_BYTES (2 * TILE_BYTES)      // 32768 (A + B)
#define GEMM_SMEM (STAGES * STAGE_BYTES)  // 98304 -> 2 CTAs/SM

__device__ signed char g_q[NPTS * DIM];   // int8 quantized rows
__device__ float g_scale[NPTS];           // per-row dequant scale
__device__ float g_sq[NPTS];
__device__ float g_loss[NPTS];
__device__ float g_psum[NPTS];
__device__ float g_nsum[NPTS];
__device__ int   g_ctr;

// ---------------------------------------------------------------------------
__device__ __forceinline__ uint32_t smem_u32(const void* p) {
    uint32_t a;
    asm("{ .reg .u64 t; cvta.to.shared.u64 t, %1; cvt.u32.u64 %0, t; }" : "=r"(a) : "l"(p));
    return a;
}
__device__ __forceinline__ void cp_async16(uint32_t dst, const void* src) {
    asm volatile("cp.async.cg.shared.global [%0], [%1], 16;" :: "r"(dst), "l"(src));
}
__device__ __forceinline__ void cp_commit() { asm volatile("cp.async.commit_group;"); }
template <int N>
__device__ __forceinline__ void cp_wait() {
    asm volatile("cp.async.wait_group %0;" :: "n"(N));
}
__device__ __forceinline__ void ldsm4(uint32_t* r, uint32_t addr) {
    asm volatile("ldmatrix.sync.aligned.m8n8.x4.shared.b16 {%0,%1,%2,%3}, [%4];"
                 : "=r"(r[0]), "=r"(r[1]), "=r"(r[2]), "=r"(r[3]) : "r"(addr));
}
__device__ __forceinline__ void imma16832(int* d, const uint32_t* a,
                                          uint32_t b0, uint32_t b1) {
    asm volatile("mma.sync.aligned.m16n8k32.row.col.s32.s8.s8.s32 "
                 "{%0,%1,%2,%3}, {%4,%5,%6,%7}, {%8,%9}, {%0,%1,%2,%3};"
                 : "+r"(d[0]), "+r"(d[1]), "+r"(d[2]), "+r"(d[3])
                 : "r"(a[0]), "r"(a[1]), "r"(a[2]), "r"(a[3]), "r"(b0), "r"(b1));
}

// ---------------------------------------------------------------------------
__device__ __forceinline__ float fast_exp(float a) {
    float y = a * 1.4426950408889634f;
    float n = rintf(y);
    float f = y - n;
    float p = 1.525273380405984e-5f;
    p = fmaf(p, f, 1.540353039338161e-4f);
    p = fmaf(p, f, 1.333355814642844e-3f);
    p = fmaf(p, f, 9.618129107628477e-3f);
    p = fmaf(p, f, 5.550410866482158e-2f);
    p = fmaf(p, f, 2.402265069591007e-1f);
    p = fmaf(p, f, 6.931471805599453e-1f);
    p = fmaf(p, f, 1.0f);
    int e = (int)n;
    return p * __int_as_float((e + 127) << 23);
}
__device__ __forceinline__ int out_index(int i, int j) {
    int lo = (i >> 3) << 3;
    unsigned rel = (unsigned)(j - lo);
    if (rel < 8u) {
        int p = j - lo - (j > i ? 1 : 0);
        return OFF_POS + i * NPOSD + p;
    }
    int p = (j < lo) ? j : (j - 8);
    return OFF_NEG + i * NNEGD + p;
}
__device__ __forceinline__ float block_sum256(float v, float* buf) {
    int t = threadIdx.x;
#pragma unroll
    for (int d = 16; d > 0; d >>= 1) v += __shfl_down_sync(0xFFFFFFFFu, v, d);
    if ((t & 31) == 0) buf[t >> 5] = v;
    __syncthreads();
    if (t < 32) {
        float x = (t < 8) ? buf[t] : 0.0f;
#pragma unroll
        for (int d = 4; d > 0; d >>= 1) x += __shfl_down_sync(0xFFFFFFFFu, x, d);
        if (t == 0) buf[0] = x;
    }
    __syncthreads();
    float r = buf[0];
    __syncthreads();
    return r;
}
__device__ __forceinline__ float block_min256(float v, float* buf) {
    int t = threadIdx.x;
#pragma unroll
    for (int d = 16; d > 0; d >>= 1) v = fminf(v, __shfl_down_sync(0xFFFFFFFFu, v, d));
    if ((t & 31) == 0) buf[t >> 5] = v;
    __syncthreads();
    if (t < 32) {
        float x = (t < 8) ? buf[t] : __int_as_float(0x7f800000);
#pragma unroll
        for (int d = 4; d > 0; d >>= 1) x = fminf(x, __shfl_down_sync(0xFFFFFFFFu, x, d));
        if (t == 0) buf[0] = x;
    }
    __syncthreads();
    float r = buf[0];
    __syncthreads();
    return r;
}

// ---------------------------------------------------------------------------
// Kernel 1: per-row max-abs + int8 quantize + exact squared norm + ctr reset
// ---------------------------------------------------------------------------
__global__ __launch_bounds__(128) void prep_kernel(const float* __restrict__ X) {
    int i = blockIdx.x, t = threadIdx.x;
    if (i == 0 && t == 0) g_ctr = 0;
    const float4* row = (const float4*)(X + (size_t)i * DIM);
    float4 x0 = row[t * 2], x1 = row[t * 2 + 1];
    float xs[8] = {x0.x, x0.y, x0.z, x0.w, x1.x, x1.y, x1.z, x1.w};

    float s = 0.0f, mx = 0.0f;
#pragma unroll
    for (int e = 0; e < 8; e++) {
        s = fmaf(xs[e], xs[e], s);
        mx = fmaxf(mx, fabsf(xs[e]));
    }
    __shared__ float sbuf[4], mbuf[4];
#pragma unroll
    for (int d = 16; d > 0; d >>= 1) {
        s += __shfl_down_sync(0xFFFFFFFFu, s, d);
        mx = fmaxf(mx, __shfl_down_sync(0xFFFFFFFFu, mx, d));
    }
    if ((t & 31) == 0) { sbuf[t >> 5] = s; mbuf[t >> 5] = mx; }
    __syncthreads();
    float maxv = fmaxf(fmaxf(mbuf[0], mbuf[1]), fmaxf(mbuf[2], mbuf[3]));
    if (t == 0) {
        g_sq[i] = sbuf[0] + sbuf[1] + sbuf[2] + sbuf[3];
        g_scale[i] = maxv * (1.0f / 127.0f);
    }
    float inv = 127.0f / maxv;
    uint32_t w0 = 0, w1 = 0;
#pragma unroll
    for (int e = 0; e < 4; e++) {
        int q = __float2int_rn(xs[e] * inv);
        w0 |= ((uint32_t)q & 255u) << (e * 8);
    }
#pragma unroll
    for (int e = 0; e < 4; e++) {
        int q = __float2int_rn(xs[e + 4] * inv);
        w1 |= ((uint32_t)q & 255u) << (e * 8);
    }
    *(uint2*)(g_q + (size_t)i * DIM + t * 8) = make_uint2(w0, w1);
}

// ---------------------------------------------------------------------------
// Kernel 2: int8 IMMA GEMM (m16n8k32), 128x128 triangular tiles (528 CTAs,
// 2 CTAs/SM), warp tile 64x32, BK=128B with SW128 XOR swizzle, 3-stage
// cp.async, single sync/iter, fused dequant+dist epilogue.
// ---------------------------------------------------------------------------
__global__ __launch_bounds__(256, 2) void gemm_dist_kernel(float* __restrict__ out) {
    extern __shared__ __align__(128) unsigned char smem_raw[];
    uint32_t sbase = smem_u32(smem_raw);

    // decode blockIdx -> (bi <= bj) over 128-row blocks
    int b = blockIdx.x;
    int bi = 0, rem = b;
    while (rem >= NB - bi) { rem -= NB - bi; bi++; }
    int bj = bi + rem;

    int tid = threadIdx.x;
    int wid = tid >> 5, lane = tid & 31;
    int wm = wid >> 2, wn = wid & 3;         // warp grid 2 x 4
    int mbase = wm * 64, nbase = wn * 32;

    // cp.async mapping: thread t -> row = t>>1 (0..127), 4 chunks of 16B
    int ldrow = tid >> 1;
    int ldq = (tid & 1) * 4;

    int acc[4][4][4];
#pragma unroll
    for (int mt = 0; mt < 4; mt++)
#pragma unroll
        for (int nt = 0; nt < 4; nt++)
#pragma unroll
            for (int e = 0; e < 4; e++) acc[mt][nt][e] = 0;

    auto issue_load = [&](int stage, int c) {
        int kk = c * 128;                    // byte offset within 1024B row
        uint32_t sA = sbase + stage * STAGE_BYTES;
        uint32_t sB = sA + TILE_BYTES;
        const signed char* ga = g_q + (size_t)(bi * 128 + ldrow) * DIM + kk;
        const signed char* gb = g_q + (size_t)(bj * 128 + ldrow) * DIM + kk;
        uint32_t rowoff = (uint32_t)ldrow * 128;
        uint32_t r7 = (uint32_t)(ldrow & 7);
#pragma unroll
        for (int j = 0; j < 4; j++) {
            uint32_t ch = (uint32_t)(ldq + j);
            uint32_t sw = rowoff + ((ch ^ r7) << 4);
            cp_async16(sA + sw, ga + ch * 16);
            cp_async16(sB + sw, gb + ch * 16);
        }
    };

#pragma unroll
    for (int s = 0; s < STAGES - 1; s++) { issue_load(s, s); cp_commit(); }

    int lrow = lane & 15, lch = lane >> 4;

    int st = 0, ld_st = STAGES - 1;
    for (int c = 0; c < KITERS; c++) {
        cp_wait<STAGES - 2>();
        __syncthreads();
        uint32_t sA = sbase + st * STAGE_BYTES;
        uint32_t sB = sA + TILE_BYTES;
#pragma unroll
        for (int ks = 0; ks < 4; ks++) {     // 4 k-steps of 32 int8
            uint32_t af[4][4], bf[2][4];
            uint32_t chsel = (uint32_t)(ks * 2 + lch);
#pragma unroll
            for (int mt = 0; mt < 4; mt++) {
                uint32_t r = (uint32_t)(mbase + mt * 16 + lrow);
                ldsm4(af[mt], sA + r * 128 + ((chsel ^ (r & 7)) << 4));
            }
#pragma unroll
            for (int nb2 = 0; nb2 < 2; nb2++) {
                uint32_t r = (uint32_t)(nbase + nb2 * 16 + lrow);
                ldsm4(bf[nb2], sB + r * 128 + ((chsel ^ (r & 7)) << 4));
            }
#pragma unroll
            for (int mt = 0; mt < 4; mt++)
#pragma unroll
                for (int nt = 0; nt < 4; nt++)
                    imma16832(acc[mt][nt], af[mt], bf[nt >> 1][nt & 1],
                              bf[nt >> 1][(nt & 1) + 2]);
        }
        if (c + STAGES - 1 < KITERS) issue_load(ld_st, c + STAGES - 1);
        cp_commit();
        st = (st == STAGES - 1) ? 0 : st + 1;
        ld_st = (ld_st == STAGES - 1) ? 0 : ld_st + 1;
    }

    // ---- epilogue: dequant + dist + scatter (direct + mirror) ----
    bool diag = (bi == bj);
    int r_in = lane >> 2, c_in = (lane & 3) * 2;
#pragma unroll
    for (int mt = 0; mt < 4; mt++) {
        int gr0 = bi * 128 + mbase + mt * 16 + r_in;
        float sq_r0 = __ldg(&g_sq[gr0]);
        float sq_r1 = __ldg(&g_sq[gr0 + 8]);
        float sc_r0 = __ldg(&g_scale[gr0]);
        float sc_r1 = __ldg(&g_scale[gr0 + 8]);
#pragma unroll
        for (int nt = 0; nt < 4; nt++) {
            int gc0 = bj * 128 + nbase + nt * 8 + c_in;
            float sq_c0 = __ldg(&g_sq[gc0]);
            float sq_c1 = __ldg(&g_sq[gc0 + 1]);
            float sc_c0 = __ldg(&g_scale[gc0]);
            float sc_c1 = __ldg(&g_scale[gc0 + 1]);
            float dot00 = (float)acc[mt][nt][0] * (sc_r0 * sc_c0);
            float dot01 = (float)acc[mt][nt][1] * (sc_r0 * sc_c1);
            float dot10 = (float)acc[mt][nt][2] * (sc_r1 * sc_c0);
            float dot11 = (float)acc[mt][nt][3] * (sc_r1 * sc_c1);
            float d00 = sqrtf(fmaxf(sq_r0 + sq_c0 - 2.0f * dot00, 1e-12f));
            float d01 = sqrtf(fmaxf(sq_r0 + sq_c1 - 2.0f * dot01, 1e-12f));
            float d10 = sqrtf(fmaxf(sq_r1 + sq_c0 - 2.0f * dot10, 1e-12f));
            float d11 = sqrtf(fmaxf(sq_r1 + sq_c1 - 2.0f * dot11, 1e-12f));
            if (diag) {
                if (gr0 != gc0)         out[out_index(gr0, gc0)] = d00;
                if (gr0 != gc0 + 1)     out[out_index(gr0, gc0 + 1)] = d01;
                if (gr0 + 8 != gc0)     out[out_index(gr0 + 8, gc0)] = d10;
                if (gr0 + 8 != gc0 + 1) out[out_index(gr0 + 8, gc0 + 1)] = d11;
            } else {
                out[out_index(gr0, gc0)] = d00;
                out[out_index(gc0, gr0)] = d00;
                out[out_index(gr0, gc0 + 1)] = d01;
                out[out_index(gc0 + 1, gr0)] = d01;
                out[out_index(gr0 + 8, gc0)] = d10;
                out[out_index(gc0, gr0 + 8)] = d10;
                out[out_index(gr0 + 8, gc0 + 1)] = d11;
                out[out_index(gc0 + 1, gr0 + 8)] = d11;
            }
        }
    }
}

// ---------------------------------------------------------------------------
// Kernel 3: per-row exact 17th-smallest (radix select) + logits; last block
// does the final deterministic reduction into out[0..3].
// ---------------------------------------------------------------------------
__global__ __launch_bounds__(256) void row_select_kernel(float* __restrict__ out) {
    int i = blockIdx.x;
    int t = threadIdx.x;
    const float* pos = out + OFF_POS + i * NPOSD;
    const float* neg = out + OFF_NEG + (size_t)i * NNEGD;

    float v[16];
    float psum = 0.0f, nsum = 0.0f;
    float minpos = __int_as_float(0x7f800000);
#pragma unroll
    for (int s = 0; s < 16; s++) {
        int idx = t + (s << 8);
        float val;
        if (idx < NPOSD) {
            val = pos[idx];
            psum += val;
            minpos = fminf(minpos, val);
        } else if (idx < NPOSD + NNEGD) {
            val = neg[idx - NPOSD];
            nsum += val;
        } else {
            val = __int_as_float(0x7f800000);
        }
        v[s] = val;
    }

    __shared__ int hist[256];
    __shared__ int wsum[8];
    __shared__ int sel[2];
    unsigned prefix = 0u;
    int k = KSEL;
#pragma unroll
    for (int pass = 0; pass < 4; pass++) {
        int shift = 24 - pass * 8;
        hist[t] = 0;
        __syncthreads();
        unsigned pm = (pass == 0) ? 0u : (0xFFFFFFFFu << (shift + 8));
#pragma unroll
        for (int s = 0; s < 16; s++) {
            unsigned bb = __float_as_uint(v[s]);
            if ((bb & pm) == prefix) atomicAdd(&hist[(bb >> shift) & 255u], 1);
        }
        __syncthreads();
        int cnt = hist[t];
        int x = cnt;
#pragma unroll
        for (int d2 = 1; d2 < 32; d2 <<= 1) {
            int y = __shfl_up_sync(0xFFFFFFFFu, x, d2);
            if ((t & 31) >= d2) x += y;
        }
        if ((t & 31) == 31) wsum[t >> 5] = x;
        __syncthreads();
        if (t < 8) {
            int y = wsum[t];
#pragma unroll
            for (int d2 = 1; d2 < 8; d2 <<= 1) {
                int z = __shfl_up_sync(0xFFu, y, d2);
                if (t >= d2) y += z;
            }
            wsum[t] = y;
        }
        __syncthreads();
        int incl = x + ((t >= 32) ? wsum[(t >> 5) - 1] : 0);
        int excl = incl - cnt;
        if (incl >= k && excl < k) { sel[0] = t; sel[1] = excl; }
        __syncthreads();
        prefix |= ((unsigned)sel[0]) << shift;
        k -= sel[1];
        __syncthreads();
    }
    float thr = __uint_as_float(prefix);

    float pe = 0.0f, ne = 0.0f;
#pragma unroll
    for (int s = 0; s < 16; s++) {
        int idx = t + (s << 8);
        float d = v[s];
        if (idx < NPOSD + NNEGD && d < thr) {
            float e = fast_exp(ALPHA_C * (1.0f - d));
            if (idx < NPOSD) pe += e; else ne += e;
        }
    }

    __shared__ float rbuf[8];
    pe     = block_sum256(pe, rbuf);
    ne     = block_sum256(ne, rbuf);
    psum   = block_sum256(psum, rbuf);
    nsum   = block_sum256(nsum, rbuf);
    minpos = block_min256(minpos, rbuf);

    if (t == 0) {
        float pl = (minpos < thr) ? pe : fast_exp(ALPHA_C * (1.0f - minpos));
        g_loss[i] = logf(pl + ne) - logf(pl);
        g_psum[i] = psum;
        g_nsum[i] = nsum;
    }

    __threadfence();
    __shared__ int lastflag;
    if (t == 0) lastflag = (atomicAdd(&g_ctr, 1) == NPTS - 1) ? 1 : 0;
    __syncthreads();
    if (lastflag) {
        float ls = 0.0f, ac = 0.0f, ps = 0.0f, ns = 0.0f;
        for (int j = t; j < NPTS; j += 256) {
            float l = g_loss[j];
            ls += l;
            ac += (l < 0.6f) ? 1.0f : 0.0f;
            ps += g_psum[j];
            ns += g_nsum[j];
        }
        ls = block_sum256(ls, rbuf);
        ac = block_sum256(ac, rbuf);
        ps = block_sum256(ps, rbuf);
        ns = block_sum256(ns, rbuf);
        if (t == 0) {
            out[0] = ls / (float)NPTS;
            out[1] = ac / (float)NPTS;
            out[2] = ps / ((float)NPTS * (float)NPOSD);
            out[3] = ns / ((float)NPTS * (float)NNEGD);
        }
    }
}

// ---------------------------------------------------------------------------
extern "C" void kernel_launch(void* const* d_in, const int* in_sizes, int n_in,
                              void* d_out, int out_size) {
    const float* X = (const float*)d_in[0];
    float* out = (float*)d_out;
    (void)in_sizes; (void)n_in; (void)out_size;

    cudaFuncSetAttribute(gemm_dist_kernel, cudaFuncAttributeMaxDynamicSharedMemorySize,
                         GEMM_SMEM);
    prep_kernel<<<NPTS, 128>>>(X);
    gemm_dist_kernel<<<NB * (NB + 1) / 2, 256, GEMM_SMEM>>>(out);
    row_select_kernel<<<NPTS, 256>>>(out);
}

// round 10
// speedup vs baseline: 3.1721x; 1.0129x over previous
#include <cuda_runtime.h>
#include <cuda_bf16.h>
#include <math.h>
#include <stdint.h>

#define NPTS 4096
#define DIM  1024
#define NPOSD 7
#define NNEGD 4088
#define KSEL 17
#define ALPHA_C 30.0f
#define OFF_POS 4
#define OFF_NEG (4 + NPTS * NPOSD)

// GEMM: CTA tile 128x128, warp tile 64x32, int8 single-pass K=1024, BK=128B
#define NB 32
#define KITERS 8
#define STAGES 3
#define TILE_BYTES (128 * 128)
#define STAGE_BYTES (2 * TILE_BYTES)
#define EPI_PITCH 133                     // floats; 133%32=5, gcd(5,32)=1
#define EPI_BYTES (128 * EPI_PITCH * 4)   // 68096
#define GEMM_SMEM (STAGES * STAGE_BYTES)  // 98304 >= EPI_BYTES

__device__ signed char g_q[NPTS * DIM];
__device__ float g_scale[NPTS];
__device__ float g_sq[NPTS];
__device__ float g_loss[NPTS];
__device__ float g_psum[NPTS];
__device__ float g_nsum[NPTS];
__device__ int   g_ctr;

// ---------------------------------------------------------------------------
__device__ __forceinline__ uint32_t smem_u32(const void* p) {
    uint32_t a;
    asm("{ .reg .u64 t; cvta.to.shared.u64 t, %1; cvt.u32.u64 %0, t; }" : "=r"(a) : "l"(p));
    return a;
}
__device__ __forceinline__ void cp_async16(uint32_t dst, const void* src) {
    asm volatile("cp.async.cg.shared.global [%0], [%1], 16;" :: "r"(dst), "l"(src));
}
__device__ __forceinline__ void cp_commit() { asm volatile("cp.async.commit_group;"); }
template <int N>
__device__ __forceinline__ void cp_wait() {
    asm volatile("cp.async.wait_group %0;" :: "n"(N));
}
__device__ __forceinline__ void ldsm4(uint32_t* r, uint32_t addr) {
    asm volatile("ldmatrix.sync.aligned.m8n8.x4.shared.b16 {%0,%1,%2,%3}, [%4];"
                 : "=r"(r[0]), "=r"(r[1]), "=r"(r[2]), "=r"(r[3]) : "r"(addr));
}
__device__ __forceinline__ void imma16832(int* d, const uint32_t* a,
                                          uint32_t b0, uint32_t b1) {
    asm volatile("mma.sync.aligned.m16n8k32.row.col.s32.s8.s8.s32 "
                 "{%0,%1,%2,%3}, {%4,%5,%6,%7}, {%8,%9}, {%0,%1,%2,%3};"
                 : "+r"(d[0]), "+r"(d[1]), "+r"(d[2]), "+r"(d[3])
                 : "r"(a[0]), "r"(a[1]), "r"(a[2]), "r"(a[3]), "r"(b0), "r"(b1));
}

// ---------------------------------------------------------------------------
__device__ __forceinline__ float fast_exp(float a) {
    float y = a * 1.4426950408889634f;
    float n = rintf(y);
    float f = y - n;
    float p = 1.525273380405984e-5f;
    p = fmaf(p, f, 1.540353039338161e-4f);
    p = fmaf(p, f, 1.333355814642844e-3f);
    p = fmaf(p, f, 9.618129107628477e-3f);
    p = fmaf(p, f, 5.550410866482158e-2f);
    p = fmaf(p, f, 2.402265069591007e-1f);
    p = fmaf(p, f, 6.931471805599453e-1f);
    p = fmaf(p, f, 1.0f);
    int e = (int)n;
    return p * __int_as_float((e + 127) << 23);
}
__device__ __forceinline__ int out_index(int i, int j) {
    int lo = (i >> 3) << 3;
    unsigned rel = (unsigned)(j - lo);
    if (rel < 8u) {
        int p = j - lo - (j > i ? 1 : 0);
        return OFF_POS + i * NPOSD + p;
    }
    int p = (j < lo) ? j : (j - 8);
    return OFF_NEG + i * NNEGD + p;
}
__device__ __forceinline__ float block_sum256(float v, float* buf) {
    int t = threadIdx.x;
#pragma unroll
    for (int d = 16; d > 0; d >>= 1) v += __shfl_down_sync(0xFFFFFFFFu, v, d);
    if ((t & 31) == 0) buf[t >> 5] = v;
    __syncthreads();
    if (t < 32) {
        float x = (t < 8) ? buf[t] : 0.0f;
#pragma unroll
        for (int d = 4; d > 0; d >>= 1) x += __shfl_down_sync(0xFFFFFFFFu, x, d);
        if (t == 0) buf[0] = x;
    }
    __syncthreads();
    float r = buf[0];
    __syncthreads();
    return r;
}
__device__ __forceinline__ float block_min256(float v, float* buf) {
    int t = threadIdx.x;
#pragma unroll
    for (int d = 16; d > 0; d >>= 1) v = fminf(v, __shfl_down_sync(0xFFFFFFFFu, v, d));
    if ((t & 31) == 0) buf[t >> 5] = v;
    __syncthreads();
    if (t < 32) {
        float x = (t < 8) ? buf[t] : __int_as_float(0x7f800000);
#pragma unroll
        for (int d = 4; d > 0; d >>= 1) x = fminf(x, __shfl_down_sync(0xFFFFFFFFu, x, d));
        if (t == 0) buf[0] = x;
    }
    __syncthreads();
    float r = buf[0];
    __syncthreads();
    return r;
}

// ---------------------------------------------------------------------------
// Kernel 1: per-row max-abs + int8 quantize + exact squared norm + ctr reset
// ---------------------------------------------------------------------------
__global__ __launch_bounds__(128) void prep_kernel(const float* __restrict__ X) {
    int i = blockIdx.x, t = threadIdx.x;
    if (i == 0 && t == 0) g_ctr = 0;
    const float4* row = (const float4*)(X + (size_t)i * DIM);
    float4 x0 = row[t * 2], x1 = row[t * 2 + 1];
    float xs[8] = {x0.x, x0.y, x0.z, x0.w, x1.x, x1.y, x1.z, x1.w};

    float s = 0.0f, mx = 0.0f;
#pragma unroll
    for (int e = 0; e < 8; e++) {
        s = fmaf(xs[e], xs[e], s);
        mx = fmaxf(mx, fabsf(xs[e]));
    }
    __shared__ float sbuf[4], mbuf[4];
#pragma unroll
    for (int d = 16; d > 0; d >>= 1) {
        s += __shfl_down_sync(0xFFFFFFFFu, s, d);
        mx = fmaxf(mx, __shfl_down_sync(0xFFFFFFFFu, mx, d));
    }
    if ((t & 31) == 0) { sbuf[t >> 5] = s; mbuf[t >> 5] = mx; }
    __syncthreads();
    float maxv = fmaxf(fmaxf(mbuf[0], mbuf[1]), fmaxf(mbuf[2], mbuf[3]));
    if (t == 0) {
        g_sq[i] = sbuf[0] + sbuf[1] + sbuf[2] + sbuf[3];
        g_scale[i] = maxv * (1.0f / 127.0f);
    }
    float inv = 127.0f / maxv;
    uint32_t w0 = 0, w1 = 0;
#pragma unroll
    for (int e = 0; e < 4; e++) {
        int q = __float2int_rn(xs[e] * inv);
        w0 |= ((uint32_t)q & 255u) << (e * 8);
    }
#pragma unroll
    for (int e = 0; e < 4; e++) {
        int q = __float2int_rn(xs[e + 4] * inv);
        w1 |= ((uint32_t)q & 255u) << (e * 8);
    }
    *(uint2*)(g_q + (size_t)i * DIM + t * 8) = make_uint2(w0, w1);
}

// ---------------------------------------------------------------------------
// Kernel 2: int8 IMMA GEMM (m16n8k32), 128x128 triangular tiles, 2 CTAs/SM,
// 3-stage cp.async, fused dequant+dist epilogue with smem-staged COALESCED
// direct + mirror writes.
// ---------------------------------------------------------------------------
__global__ __launch_bounds__(256, 2) void gemm_dist_kernel(float* __restrict__ out) {
    extern __shared__ __align__(128) unsigned char smem_raw[];
    uint32_t sbase = smem_u32(smem_raw);

    int b = blockIdx.x;
    int bi = 0, rem = b;
    while (rem >= NB - bi) { rem -= NB - bi; bi++; }
    int bj = bi + rem;

    int tid = threadIdx.x;
    int wid = tid >> 5, lane = tid & 31;
    int wm = wid >> 2, wn = wid & 3;
    int mbase = wm * 64, nbase = wn * 32;

    int ldrow = tid >> 1;
    int ldq = (tid & 1) * 4;

    int acc[4][4][4];
#pragma unroll
    for (int mt = 0; mt < 4; mt++)
#pragma unroll
        for (int nt = 0; nt < 4; nt++)
#pragma unroll
            for (int e = 0; e < 4; e++) acc[mt][nt][e] = 0;

    auto issue_load = [&](int stage, int c) {
        int kk = c * 128;
        uint32_t sA = sbase + stage * STAGE_BYTES;
        uint32_t sB = sA + TILE_BYTES;
        const signed char* ga = g_q + (size_t)(bi * 128 + ldrow) * DIM + kk;
        const signed char* gb = g_q + (size_t)(bj * 128 + ldrow) * DIM + kk;
        uint32_t rowoff = (uint32_t)ldrow * 128;
        uint32_t r7 = (uint32_t)(ldrow & 7);
#pragma unroll
        for (int j = 0; j < 4; j++) {
            uint32_t ch = (uint32_t)(ldq + j);
            uint32_t sw = rowoff + ((ch ^ r7) << 4);
            cp_async16(sA + sw, ga + ch * 16);
            cp_async16(sB + sw, gb + ch * 16);
        }
    };

#pragma unroll
    for (int s = 0; s < STAGES - 1; s++) { issue_load(s, s); cp_commit(); }

    int lrow = lane & 15, lch = lane >> 4;

    int st = 0, ld_st = STAGES - 1;
    for (int c = 0; c < KITERS; c++) {
        cp_wait<STAGES - 2>();
        __syncthreads();
        uint32_t sA = sbase + st * STAGE_BYTES;
        uint32_t sB = sA + TILE_BYTES;
#pragma unroll
        for (int ks = 0; ks < 4; ks++) {
            uint32_t af[4][4], bf[2][4];
            uint32_t chsel = (uint32_t)(ks * 2 + lch);
#pragma unroll
            for (int mt = 0; mt < 4; mt++) {
                uint32_t r = (uint32_t)(mbase + mt * 16 + lrow);
                ldsm4(af[mt], sA + r * 128 + ((chsel ^ (r & 7)) << 4));
            }
#pragma unroll
            for (int nb2 = 0; nb2 < 2; nb2++) {
                uint32_t r = (uint32_t)(nbase + nb2 * 16 + lrow);
                ldsm4(bf[nb2], sB + r * 128 + ((chsel ^ (r & 7)) << 4));
            }
#pragma unroll
            for (int mt = 0; mt < 4; mt++)
#pragma unroll
                for (int nt = 0; nt < 4; nt++)
                    imma16832(acc[mt][nt], af[mt], bf[nt >> 1][nt & 1],
                              bf[nt >> 1][(nt & 1) + 2]);
        }
        if (c + STAGES - 1 < KITERS) issue_load(ld_st, c + STAGES - 1);
        cp_commit();
        st = (st == STAGES - 1) ? 0 : st + 1;
        ld_st = (ld_st == STAGES - 1) ? 0 : ld_st + 1;
    }

    // ---- epilogue: dequant + dist -> smem staging -> coalesced writes ----
    __syncthreads();                     // all warps done with pipeline smem
    float* S = (float*)smem_raw;
    int r_in = lane >> 2, c_in = (lane & 3) * 2;
#pragma unroll
    for (int mt = 0; mt < 4; mt++) {
        int lr0 = mbase + mt * 16 + r_in;
        int gr0 = bi * 128 + lr0;
        float sq_r0 = __ldg(&g_sq[gr0]);
        float sq_r1 = __ldg(&g_sq[gr0 + 8]);
        float sc_r0 = __ldg(&g_scale[gr0]);
        float sc_r1 = __ldg(&g_scale[gr0 + 8]);
#pragma unroll
        for (int nt = 0; nt < 4; nt++) {
            int lc0 = nbase + nt * 8 + c_in;
            int gc0 = bj * 128 + lc0;
            float sq_c0 = __ldg(&g_sq[gc0]);
            float sq_c1 = __ldg(&g_sq[gc0 + 1]);
            float sc_c0 = __ldg(&g_scale[gc0]);
            float sc_c1 = __ldg(&g_scale[gc0 + 1]);
            float dot00 = (float)acc[mt][nt][0] * (sc_r0 * sc_c0);
            float dot01 = (float)acc[mt][nt][1] * (sc_r0 * sc_c1);
            float dot10 = (float)acc[mt][nt][2] * (sc_r1 * sc_c0);
            float dot11 = (float)acc[mt][nt][3] * (sc_r1 * sc_c1);
            S[lr0 * EPI_PITCH + lc0]           = sqrtf(fmaxf(sq_r0 + sq_c0 - 2.0f * dot00, 1e-12f));
            S[lr0 * EPI_PITCH + lc0 + 1]       = sqrtf(fmaxf(sq_r0 + sq_c1 - 2.0f * dot01, 1e-12f));
            S[(lr0 + 8) * EPI_PITCH + lc0]     = sqrtf(fmaxf(sq_r1 + sq_c0 - 2.0f * dot10, 1e-12f));
            S[(lr0 + 8) * EPI_PITCH + lc0 + 1] = sqrtf(fmaxf(sq_r1 + sq_c1 - 2.0f * dot11, 1e-12f));
        }
    }
    __syncthreads();

    // direct pass: warp handles rows, 32 consecutive cols per trip (coalesced)
    for (int rr = wid; rr < 128; rr += 8) {
        int gi = bi * 128 + rr;
#pragma unroll
        for (int q = 0; q < 4; q++) {
            int cc = lane + q * 32;
            int gj = bj * 128 + cc;
            if (gi != gj) out[out_index(gi, gj)] = S[rr * EPI_PITCH + cc];
        }
    }
    // mirror pass (off-diag only): transposed smem read, coalesced writes
    if (bi != bj) {
        for (int rr = wid; rr < 128; rr += 8) {
            int gj = bj * 128 + rr;
#pragma unroll
            for (int q = 0; q < 4; q++) {
                int cc = lane + q * 32;
                out[out_index(gj, bi * 128 + cc)] = S[cc * EPI_PITCH + rr];
            }
        }
    }
}

// ---------------------------------------------------------------------------
// Kernel 3: per-row exact 17th-smallest (radix select, per-warp histograms)
// + logits; last block does the final deterministic reduction.
// ---------------------------------------------------------------------------
__global__ __launch_bounds__(256) void row_select_kernel(float* __restrict__ out) {
    int i = blockIdx.x;
    int t = threadIdx.x;
    int w = t >> 5;
    const float* pos = out + OFF_POS + i * NPOSD;
    const float* neg = out + OFF_NEG + (size_t)i * NNEGD;

    float v[16];
    float psum = 0.0f, nsum = 0.0f;
    float minpos = __int_as_float(0x7f800000);
#pragma unroll
    for (int s = 0; s < 16; s++) {
        int idx = t + (s << 8);
        float val;
        if (idx < NPOSD) {
            val = pos[idx];
            psum += val;
            minpos = fminf(minpos, val);
        } else if (idx < NPOSD + NNEGD) {
            val = neg[idx - NPOSD];
            nsum += val;
        } else {
            val = __int_as_float(0x7f800000);
        }
        v[s] = val;
    }

    __shared__ int hist8[8][256];
    __shared__ int wsum[8];
    __shared__ int sel[2];
    unsigned prefix = 0u;
    int k = KSEL;
#pragma unroll
    for (int pass = 0; pass < 4; pass++) {
        int shift = 24 - pass * 8;
#pragma unroll
        for (int ww = 0; ww < 8; ww++) hist8[ww][t] = 0;
        __syncthreads();
        unsigned pm = (pass == 0) ? 0u : (0xFFFFFFFFu << (shift + 8));
#pragma unroll
        for (int s = 0; s < 16; s++) {
            unsigned bb = __float_as_uint(v[s]);
            if ((bb & pm) == prefix) atomicAdd(&hist8[w][(bb >> shift) & 255u], 1);
        }
        __syncthreads();
        int cnt = hist8[0][t] + hist8[1][t] + hist8[2][t] + hist8[3][t]
                + hist8[4][t] + hist8[5][t] + hist8[6][t] + hist8[7][t];
        int x = cnt;
#pragma unroll
        for (int d2 = 1; d2 < 32; d2 <<= 1) {
            int y = __shfl_up_sync(0xFFFFFFFFu, x, d2);
            if ((t & 31) >= d2) x += y;
        }
        if ((t & 31) == 31) wsum[t >> 5] = x;
        __syncthreads();
        if (t < 8) {
            int y = wsum[t];
#pragma unroll
            for (int d2 = 1; d2 < 8; d2 <<= 1) {
                int z = __shfl_up_sync(0xFFu, y, d2);
                if (t >= d2) y += z;
            }
            wsum[t] = y;
        }
        __syncthreads();
        int incl = x + ((t >= 32) ? wsum[(t >> 5) - 1] : 0);
        int excl = incl - cnt;
        if (incl >= k && excl < k) { sel[0] = t; sel[1] = excl; }
        __syncthreads();
        prefix |= ((unsigned)sel[0]) << shift;
        k -= sel[1];
        __syncthreads();
    }
    float thr = __uint_as_float(prefix);

    float pe = 0.0f, ne = 0.0f;
#pragma unroll
    for (int s = 0; s < 16; s++) {
        int idx = t + (s << 8);
        float d = v[s];
        if (idx < NPOSD + NNEGD && d < thr) {
            float e = fast_exp(ALPHA_C * (1.0f - d));
            if (idx < NPOSD) pe += e; else ne += e;
        }
    }

    __shared__ float rbuf[8];
    pe     = block_sum256(pe, rbuf);
    ne     = block_sum256(ne, rbuf);
    psum   = block_sum256(psum, rbuf);
    nsum   = block_sum256(nsum, rbuf);
    minpos = block_min256(minpos, rbuf);

    if (t == 0) {
        float pl = (minpos < thr) ? pe : fast_exp(ALPHA_C * (1.0f - minpos));
        g_loss[i] = logf(pl + ne) - logf(pl);
        g_psum[i] = psum;
        g_nsum[i] = nsum;
    }

    __threadfence();
    __shared__ int lastflag;
    if (t == 0) lastflag = (atomicAdd(&g_ctr, 1) == NPTS - 1) ? 1 : 0;
    __syncthreads();
    if (lastflag) {
        float ls = 0.0f, ac = 0.0f, ps = 0.0f, ns = 0.0f;
        for (int j = t; j < NPTS; j += 256) {
            float l = g_loss[j];
            ls += l;
            ac += (l < 0.6f) ? 1.0f : 0.0f;
            ps += g_psum[j];
            ns += g_nsum[j];
        }
        ls = block_sum256(ls, rbuf);
        ac = block_sum256(ac, rbuf);
        ps = block_sum256(ps, rbuf);
        ns = block_sum256(ns, rbuf);
        if (t == 0) {
            out[0] = ls / (float)NPTS;
            out[1] = ac / (float)NPTS;
            out[2] = ps / ((float)NPTS * (float)NPOSD);
            out[3] = ns / ((float)NPTS * (float)NNEGD);
        }
    }
}

// ---------------------------------------------------------------------------
extern "C" void kernel_launch(void* const* d_in, const int* in_sizes, int n_in,
                              void* d_out, int out_size) {
    const float* X = (const float*)d_in[0];
    float* out = (float*)d_out;
    (void)in_sizes; (void)n_in; (void)out_size;

    cudaFuncSetAttribute(gemm_dist_kernel, cudaFuncAttributeMaxDynamicSharedMemorySize,
                         GEMM_SMEM);
    prep_kernel<<<NPTS, 128>>>(X);
    gemm_dist_kernel<<<NB * (NB + 1) / 2, 256, GEMM_SMEM>>>(out);
    row_select_kernel<<<NPTS, 256>>>(out);
}